// round 13
// baseline (speedup 1.0000x reference)
#include <cuda_runtime.h>
#include <cstdint>

// Depthwise 3D conv 3x3x3, SAME, stride 1.
// x: (4,16,112,112,64) f32 NDHWC; w: (3,3,3,1,64) f32.
//
// R13 vs R12: re-tile to HPT=3 (thread = 2 channels x 8 w x 3 h-rows).
// Window = 5 rows x 10 ull -> 150 input LDG per thread for 24 outputs
// (6.25/output vs 7.5), keeping the proven 10-deep load bursts. Full 9-tap
// kd plane held in registers (no rotation). l1tex traffic -18%/output.
// Interior/edge split retained; __launch_bounds__(64,10) (cap 102 regs).

#define N_  4
#define D_  16
#define H_  112
#define W_  112
#define C_  64
#define WPT 8
#define HPT 3
#define CS  (C_ / 2)   // 32 ull per spatial position
#define ROWSTEP (W_ * CS)

typedef unsigned long long ull;

__device__ __forceinline__ ull ffma2(ull a, ull b, ull c) {
    ull d;
    asm("fma.rn.f32x2 %0, %1, %2, %3;" : "=l"(d) : "l"(a), "l"(b), "l"(c));
    return d;
}

template <bool INT>
__device__ __forceinline__ void conv_body(
    const ull* __restrict__ xp, const ull* __restrict__ swp,
    ull* __restrict__ out, int n, int d, int h0, int w0, int tx) {

    const bool wlo = INT || (w0 > 0);
    const bool whi = INT || (w0 + WPT < W_);

    ull acc[HPT][WPT];
#pragma unroll
    for (int j = 0; j < HPT; j++)
#pragma unroll
        for (int i = 0; i < WPT; i++) acc[j][i] = 0ull;

#pragma unroll
    for (int kd = 0; kd < 3; kd++) {
        const int zd = d + kd - 1;
        if (!INT && (unsigned)zd >= D_) continue;

        // full 9-tap plane for this kd (channel pair tx), loaded once
        ull wt[3][3];
#pragma unroll
        for (int kh = 0; kh < 3; kh++)
#pragma unroll
            for (int kw = 0; kw < 3; kw++)
                wt[kh][kw] = swp[((kd * 3 + kh) * 3 + kw) * CS + tx];

        // pointer to (n, zd, h0-1, w0, tx); advances one h-row per r
        const ull* rowp =
            xp + ((((n * D_ + zd) * H_ + (h0 - 1)) * W_ + w0) * CS + tx);

#pragma unroll
        for (int r = 0; r < HPT + 2; r++) {    // zh = h0-1 .. h0+3
            const int zh = h0 - 1 + r;
            const bool rowOk = INT || ((unsigned)zh < H_);

            if (rowOk) {
                // batched 10-LDG row preload, immediate offsets
                ull rv[WPT + 2];
                rv[0] = wlo ? rowp[-CS] : 0ull;
#pragma unroll
                for (int q = 0; q < WPT; q++)
                    rv[q + 1] = rowp[q * CS];
                rv[WPT + 1] = whi ? rowp[WPT * CS] : 0ull;

                // row r feeds outputs j with kh = r-j, 0 <= r-j <= 2
#pragma unroll
                for (int j = 0; j < HPT; j++) {
                    if (j <= r && r <= j + 2) {
                        const int kh = r - j;
#pragma unroll
                        for (int i = 0; i < WPT; i++) {
                            acc[j][i] = ffma2(rv[i],     wt[kh][0], acc[j][i]);
                            acc[j][i] = ffma2(rv[i + 1], wt[kh][1], acc[j][i]);
                            acc[j][i] = ffma2(rv[i + 2], wt[kh][2], acc[j][i]);
                        }
                    }
                }
            }
            rowp += ROWSTEP;
        }
    }

    ull* __restrict__ op =
        out + ((((n * D_ + d) * H_ + h0) * W_ + w0) * CS + tx);
#pragma unroll
    for (int j = 0; j < HPT; j++) {
        if (INT || (unsigned)(h0 + j) < H_) {
#pragma unroll
            for (int i = 0; i < WPT; i++)
                op[(j * W_ + i) * CS] = acc[j][i];
        }
    }
}

__global__ void __launch_bounds__(64, 10)
dwconv3d_kernel(const float* __restrict__ x,
                const float* __restrict__ wgt,
                float* __restrict__ out) {
    const ull* __restrict__ swp = reinterpret_cast<const ull*>(wgt);
    const ull* __restrict__ xp  = reinterpret_cast<const ull*>(x);
    ull* __restrict__ op        = reinterpret_cast<ull*>(out);

    const int tx = threadIdx.x;                        // channel pair 0..31
    const int h0 = blockIdx.y * 6 + threadIdx.y * 3;   // 0,3,...,111
    const int w0 = blockIdx.x * WPT;                   // 0..104
    const int nd = blockIdx.z;
    const int n  = nd >> 4;
    const int d  = nd & 15;

    // Block-uniform interior: rows by*6-1 .. by*6+7 all in [0,111],
    // plus no d/w halo clamping anywhere in the block.
    const bool interior =
        (d >= 1) && (d <= 14) &&
        (blockIdx.y >= 1) && (blockIdx.y <= 17) &&
        (blockIdx.x >= 1) && (blockIdx.x <= (W_ / WPT) - 2);

    if (interior)
        conv_body<true>(xp, swp, op, n, d, h0, w0, tx);
    else
        conv_body<false>(xp, swp, op, n, d, h0, w0, tx);
}

extern "C" void kernel_launch(void* const* d_in, const int* in_sizes, int n_in,
                              void* d_out, int out_size) {
    const float* x = (const float*)d_in[0];
    const float* w = (const float*)d_in[1];
    float* o = (float*)d_out;

    dim3 block(32, 2, 1);                        // 64 threads
    // grid.y = ceil(112 / 6) = 19 (last row-block guarded in edge path)
    dim3 grid(W_ / WPT, (H_ + 5) / 6, N_ * D_);  // 14 x 19 x 64
    dwconv3d_kernel<<<grid, block>>>(x, w, o);
}